// round 15
// baseline (speedup 1.0000x reference)
#include <cuda_runtime.h>

#define SQ   512
#define BB   64
#define FIN  512
#define HH   512
#define G4   2048
#define NB   128
#define NT   256

typedef unsigned long long ull;

// Static device scratch (allocation-guard safe)
__device__ float g_xg[(long long)SQ * BB * G4];   // input-projection gates [S, B, 4H]
__device__ float g_c [(long long)SQ * BB * HH];   // fallback c-state history
__device__ int   g_flag[SQ * NB];                 // per (step, block) ready flags

// ---------------- PTX helpers ----------------
__device__ __forceinline__ void ffma2(ull& d, ull a, ull b) {
    asm("fma.rn.f32x2 %0, %1, %2, %0;" : "+l"(d) : "l"(a), "l"(b));
}
__device__ __forceinline__ ull packf2(float x, float y) {
    ull d; asm("mov.b64 %0, {%1, %2};" : "=l"(d) : "f"(x), "f"(y)); return d;
}
__device__ __forceinline__ float2 unpackf2(ull v) {
    float2 r; asm("mov.b64 {%0, %1}, %2;" : "=f"(r.x), "=f"(r.y) : "l"(v)); return r;
}
__device__ __forceinline__ int ld_acq(const int* p) {
    int v; asm volatile("ld.acquire.gpu.global.s32 %0, [%1];" : "=r"(v) : "l"(p) : "memory");
    return v;
}
__device__ __forceinline__ void st_rel(int* p, int v) {
    asm volatile("st.release.gpu.global.s32 [%0], %1;" :: "l"(p), "r"(v) : "memory");
}
__device__ __forceinline__ float fex2(float x) {
    float r; asm("ex2.approx.ftz.f32 %0, %1;" : "=f"(r) : "f"(x)); return r;
}
__device__ __forceinline__ float frcp(float x) {
    float r; asm("rcp.approx.ftz.f32 %0, %1;" : "=f"(r) : "f"(x)); return r;
}
__device__ __forceinline__ float fsig(float x) {
    return frcp(1.0f + fex2(-1.4426950408889634f * x));
}
__device__ __forceinline__ float ftanh(float x) {
    return 1.0f - 2.0f * frcp(1.0f + fex2(2.8853900817779268f * x));
}

// ---------------------------------------------------------------------------
__global__ void flag_init() { g_flag[blockIdx.x * NB + threadIdx.x] = 0; }

// ---------------------------------------------------------------------------
// Kernel A: XG = seq @ w_ih^T + (b_ih + b_hh). (Unchanged, ~1.75ms.)
// ---------------------------------------------------------------------------
__global__ __launch_bounds__(256)
void gemm_in(const float* __restrict__ A, const float* __restrict__ W,
             const float* __restrict__ bih, const float* __restrict__ bhh,
             float* __restrict__ C)
{
    __shared__ __align__(16) float As[8][132];
    __shared__ __align__(16) float Bs[8][132];

    const int tid  = threadIdx.x;
    const int tx   = tid & 15;
    const int ty   = tid >> 4;
    const int m0   = blockIdx.y * 128;
    const int n0   = blockIdx.x * 128;
    const int lrow = tid >> 1;
    const int lk4  = (tid & 1) * 4;

    const float* Aptr = A + (size_t)(m0 + lrow) * FIN + lk4;
    const float* Wptr = W + (size_t)(n0 + lrow) * FIN + lk4;

    ull acc2[4][8];
    #pragma unroll
    for (int i = 0; i < 4; i++)
        #pragma unroll
        for (int j = 0; j < 8; j++) acc2[i][j] = 0ULL;

    float4 ra = *(const float4*)(Aptr);
    float4 rb = *(const float4*)(Wptr);

    for (int kb = 0; kb < 64; kb++) {
        As[lk4 + 0][lrow] = ra.x; As[lk4 + 1][lrow] = ra.y;
        As[lk4 + 2][lrow] = ra.z; As[lk4 + 3][lrow] = ra.w;
        Bs[lk4 + 0][lrow] = rb.x; Bs[lk4 + 1][lrow] = rb.y;
        Bs[lk4 + 2][lrow] = rb.z; Bs[lk4 + 3][lrow] = rb.w;
        __syncthreads();

        if (kb < 63) {
            ra = *(const float4*)(Aptr + (kb + 1) * 8);
            rb = *(const float4*)(Wptr + (kb + 1) * 8);
        }

        #pragma unroll
        for (int kk = 0; kk < 8; kk++) {
            ulonglong2 a01 = *(const ulonglong2*)&As[kk][ty * 8];
            ulonglong2 a23 = *(const ulonglong2*)&As[kk][ty * 8 + 4];
            ull av[4] = {a01.x, a01.y, a23.x, a23.y};
            float4 b0 = *(const float4*)&Bs[kk][tx * 8];
            float4 b1 = *(const float4*)&Bs[kk][tx * 8 + 4];
            ull rbk[8];
            rbk[0] = packf2(b0.x, b0.x); rbk[1] = packf2(b0.y, b0.y);
            rbk[2] = packf2(b0.z, b0.z); rbk[3] = packf2(b0.w, b0.w);
            rbk[4] = packf2(b1.x, b1.x); rbk[5] = packf2(b1.y, b1.y);
            rbk[6] = packf2(b1.z, b1.z); rbk[7] = packf2(b1.w, b1.w);
            #pragma unroll
            for (int i2 = 0; i2 < 4; i2++)
                #pragma unroll
                for (int j = 0; j < 8; j++)
                    ffma2(acc2[i2][j], av[i2], rbk[j]);
        }
        __syncthreads();
    }

    float bias[8];
    #pragma unroll
    for (int j = 0; j < 8; j++) {
        int n = n0 + tx * 8 + j;
        bias[j] = bih[n] + bhh[n];
    }
    #pragma unroll
    for (int i2 = 0; i2 < 4; i2++) {
        float r0[8], r1[8];
        #pragma unroll
        for (int j = 0; j < 8; j++) {
            float2 v = unpackf2(acc2[i2][j]);
            r0[j] = v.x + bias[j];
            r1[j] = v.y + bias[j];
        }
        int m = m0 + ty * 8 + 2 * i2;
        float* p0 = C + (size_t)m * G4 + n0 + tx * 8;
        float* p1 = p0 + G4;
        *(float4*)(p0)     = make_float4(r0[0], r0[1], r0[2], r0[3]);
        *(float4*)(p0 + 4) = make_float4(r0[4], r0[5], r0[6], r0[7]);
        *(float4*)(p1)     = make_float4(r1[0], r1[1], r1[2], r1[3]);
        *(float4*)(p1 + 4) = make_float4(r1[4], r1[5], r1[6], r1[7]);
    }
}

// ---------------------------------------------------------------------------
// Kernel B v5: pipelined crossbar-minimal persistent recurrence.
// Block owns 4 h-columns n0 = 4*bid. Lane l: ks = l&7 (k-slice of 32 within a
// 256-k half), g = l>>3 (gate). Warp w = batch group (8 batches).
// Thread tile: 8 batches x 4 cols for gate g, 32 k per half.
//
// Step pipeline:
//   wait flag -> stage half0 -> sync
//   [LDG half1 -> regs || compute half0] -> STS half1 -> sync -> compute half1
//   shfl-reduce over ks -> partials -> epilogue -> publish
//
// smem (strides in floats; all 16B-aligned):
//   sW[g][col][sl][kk] : g*2336 + col*576 + sl*36 + kk   (sl = 16 slices of 32)
//     w-LDS lane quads: 8g + 9ks  (bijection on Z32 -> exactly 4 wavefronts)
//   sH0/sH1[b][ks][kk] : b*288 + ks*36 + kk
//     h-LDS lane quads: 9ks, g broadcast -> 1 wavefront
//   sP[b][r]: b*20 + r
// ---------------------------------------------------------------------------
#define WGS  2336
#define WCS  576
#define SLS  36
#define HBS  288
#define SW_FLOATS (4 * WGS)               // 9344
#define SHH_FLOATS (64 * HBS)             // 18432 (per half)
#define SP_FLOATS (64 * 20)               // 1280
#define SMEM_FLOATS (SW_FLOATS + 2 * SHH_FLOATS + SP_FLOATS)   // 47488
#define SMEM_BYTES  (SMEM_FLOATS * 4)                          // 189952

__device__ __forceinline__ void mv_half(const float* __restrict__ wb,
                                        const float* __restrict__ hb,
                                        ull acc[8][4])
{
    #pragma unroll
    for (int q = 0; q < 8; q++) {
        ulonglong2 w0 = *(const ulonglong2*)(wb + q * 4);
        ulonglong2 w1 = *(const ulonglong2*)(wb + WCS + q * 4);
        ulonglong2 w2 = *(const ulonglong2*)(wb + 2 * WCS + q * 4);
        ulonglong2 w3 = *(const ulonglong2*)(wb + 3 * WCS + q * 4);
        #pragma unroll
        for (int bb = 0; bb < 8; bb++) {
            ulonglong2 hv = *(const ulonglong2*)(hb + bb * HBS + q * 4);
            ffma2(acc[bb][0], hv.x, w0.x); ffma2(acc[bb][0], hv.y, w0.y);
            ffma2(acc[bb][1], hv.x, w1.x); ffma2(acc[bb][1], hv.y, w1.y);
            ffma2(acc[bb][2], hv.x, w2.x); ffma2(acc[bb][2], hv.y, w2.y);
            ffma2(acc[bb][3], hv.x, w3.x); ffma2(acc[bb][3], hv.y, w3.y);
        }
    }
}

__global__ __launch_bounds__(NT, 1)
void lstm_persist(const float* __restrict__ xg,
                  const float* __restrict__ Whh,
                  float* __restrict__ hout,   // [S][B][H] hs output + h history
                  float* __restrict__ cout)   // [S][B][H] cs output
{
    extern __shared__ __align__(16) float sm[];
    float* sW  = sm;
    float* sH0 = sm + SW_FLOATS;
    float* sH1 = sH0 + SHH_FLOATS;
    float* sP  = sH1 + SHH_FLOATS;

    const int tid = threadIdx.x;
    const int w   = tid >> 5;
    const int l   = tid & 31;
    const int ks  = l & 7;
    const int g   = l >> 3;
    const int n0  = blockIdx.x * 4;
    const int bid = blockIdx.x;

    // ---- Stage the 16 w_hh rows once ----
    #pragma unroll
    for (int i = 0; i < 8; i++) {
        int s  = tid + NT * i;              // 0..2047 float4 units
        int r  = s >> 7;                    // 0..15
        int k4 = (s & 127) * 4;             // 0..508
        int gg = r >> 2, col = r & 3;
        float4 v = *(const float4*)(Whh + (size_t)(gg * HH + n0 + col) * HH + k4);
        *(float4*)(sW + gg * WGS + col * WCS + (k4 >> 5) * SLS + (k4 & 31)) = v;
    }
    __syncthreads();

    // Epilogue identity (thread owns (eb, ec) forever; c in a register)
    const int eb = w * 8 + (l >> 2);
    const int ec = l & 3;
    float creg = 0.0f;

    const float* wb0 = sW + g * WGS + ks * SLS;          // half0 w slice
    const float* wb1 = wb0 + 8 * SLS;                    // half1 w slice
    const float* hb0 = sH0 + (w * 8) * HBS + ks * SLS;
    const float* hb1 = sH1 + (w * 8) * HBS + ks * SLS;

    for (int t = 0; t < SQ; t++) {
        // Prefetch xg[t] (independent of the flag)
        const float* xq = xg + (size_t)t * BB * G4 + (size_t)eb * G4 + n0 + ec;
        float x0 = xq[0], x1 = xq[512], x2 = xq[1024], x3 = xq[1536];

        float pre0 = x0, pre1 = x1, pre2 = x2, pre3 = x3;

        if (t > 0) {
            // Wait for all 128 blocks to publish step t-1
            if (tid < NB) {
                while (ld_acq(&g_flag[(t - 1) * NB + tid]) == 0) {}
            }
            __syncthreads();

            const float* hp = hout + (size_t)(t - 1) * BB * HH;

            // ---- Stage half0 (64KB): LDG.128 -> STS.128 ----
            #pragma unroll
            for (int i = 0; i < 16; i++) {
                int s  = tid + NT * i;        // 0..4095 f4 units
                int b  = s >> 6;
                int k4 = (s & 63) * 4;        // 0..252
                float4 v = *(const float4*)(hp + b * HH + k4);
                *(float4*)(sH0 + b * HBS + (k4 >> 5) * SLS + (k4 & 31)) = v;
            }
            __syncthreads();

            ull acc[8][4];
            #pragma unroll
            for (int bb = 0; bb < 8; bb++)
                #pragma unroll
                for (int j = 0; j < 4; j++) acc[bb][j] = 0ULL;

            // ---- Prefetch half1 into registers (overlaps compute below) ----
            float4 pf[16];
            #pragma unroll
            for (int i = 0; i < 16; i++) {
                int s  = tid + NT * i;
                int b  = s >> 6;
                int k4 = (s & 63) * 4;
                pf[i] = *(const float4*)(hp + b * HH + 256 + k4);
            }

            // ---- Compute half0 (hides the half1 LDG latency) ----
            mv_half(wb0, hb0, acc);

            // ---- Store half1, then compute it ----
            #pragma unroll
            for (int i = 0; i < 16; i++) {
                int s  = tid + NT * i;
                int b  = s >> 6;
                int k4 = (s & 63) * 4;
                *(float4*)(sH1 + b * HBS + (k4 >> 5) * SLS + (k4 & 31)) = pf[i];
            }
            __syncthreads();

            mv_half(wb1, hb1, acc);

            // ---- Collapse f32x2 + butterfly over ks (lane bits 0..2) ----
            float s_[8][4];
            #pragma unroll
            for (int bb = 0; bb < 8; bb++)
                #pragma unroll
                for (int j = 0; j < 4; j++) {
                    float2 v = unpackf2(acc[bb][j]);
                    float x = v.x + v.y;
                    x += __shfl_xor_sync(0xffffffffu, x, 1);
                    x += __shfl_xor_sync(0xffffffffu, x, 2);
                    x += __shfl_xor_sync(0xffffffffu, x, 4);
                    s_[bb][j] = x;
                }

            // ks==0 lanes publish partials: sP[b][g*4 + col]
            if (ks == 0) {
                #pragma unroll
                for (int bb = 0; bb < 8; bb++)
                    *(float4*)(sP + (w * 8 + bb) * 20 + g * 4) =
                        make_float4(s_[bb][0], s_[bb][1], s_[bb][2], s_[bb][3]);
            }
            __syncthreads();

            const float* pp = sP + eb * 20 + ec;
            pre0 += pp[0];
            pre1 += pp[4];
            pre2 += pp[8];
            pre3 += pp[12];
        }

        // ---- Gate epilogue (order i, f, g, o); bias folded into xg ----
        float cn = fsig(pre1) * creg + fsig(pre0) * ftanh(pre2);
        float hn = fsig(pre3) * ftanh(cn);
        creg = cn;

        size_t off = (size_t)t * BB * HH + (size_t)eb * HH + n0 + ec;
        hout[off] = hn;
        cout[off] = cn;

        // Publish step t
        __syncthreads();
        if (tid == 0) st_rel(&g_flag[t * NB + bid], 1);
    }
}

// ---------------------------------------------------------------------------
// Host
// ---------------------------------------------------------------------------
extern "C" void kernel_launch(void* const* d_in, const int* in_sizes, int n_in,
                              void* d_out, int out_size)
{
    const float* seq = (const float*)d_in[0];
    const float* wih = (const float*)d_in[1];
    const float* whh = (const float*)d_in[2];
    const float* bih = (const float*)d_in[3];
    const float* bhh = (const float*)d_in[4];
    float* out = (float*)d_out;

    float *xgp, *cscr;
    cudaGetSymbolAddress((void**)&xgp, g_xg);
    cudaGetSymbolAddress((void**)&cscr, g_c);

    const size_t SBH = (size_t)SQ * BB * HH;
    float* cbase = ((size_t)out_size >= 2 * SBH) ? (out + SBH) : cscr;

    flag_init<<<SQ, NB>>>();

    dim3 gg(G4 / 128, (SQ * BB) / 128);            // (16, 256)
    gemm_in<<<gg, 256>>>(seq, wih, bih, bhh, xgp);

    cudaFuncSetAttribute(lstm_persist, cudaFuncAttributeMaxDynamicSharedMemorySize,
                         SMEM_BYTES);
    lstm_persist<<<NB, NT, SMEM_BYTES>>>(xgp, whh, out, cbase);
}